// round 1
// baseline (speedup 1.0000x reference)
#include <cuda_runtime.h>
#include <cstdint>

#define BB 65536
#define XX 362
#define AA 3
#define GS 19

#define MT 128          // rows per MLP tile
#define TILES (BB / MT) // 512
#define STRH1 108       // smem stride for h1/h3 (conflict-free A-frag loads)
#define STRW  132       // smem stride for weight chunks (conflict-free B-frag loads)
#define STRH2 132       // smem stride for h2 chunk

// ---------------- device scratch (no allocations allowed) ----------------
__device__ int   g_count[AA];
__device__ int   g_perm[AA * BB];
__device__ float g_att[BB * 6];
__device__ int   g_idx[BB * 6];

// ---------------- helpers ----------------
__device__ __forceinline__ unsigned tf32r(float f) {
    unsigned u;
    asm("cvt.rna.tf32.f32 %0, %1;" : "=r"(u) : "f"(f));
    return u;
}

__device__ __forceinline__ void mma_tf32(float c[4],
                                         unsigned a0, unsigned a1, unsigned a2, unsigned a3,
                                         unsigned b0, unsigned b1) {
    asm volatile(
        "mma.sync.aligned.m16n8k8.row.col.f32.tf32.tf32.f32 "
        "{%0,%1,%2,%3}, {%4,%5,%6,%7}, {%8,%9}, {%0,%1,%2,%3};"
        : "+f"(c[0]), "+f"(c[1]), "+f"(c[2]), "+f"(c[3])
        : "r"(a0), "r"(a1), "r"(a2), "r"(a3), "r"(b0), "r"(b1));
}

// ---------------- kernel 0: reset bucket counters ----------------
__global__ void zero_counts_kernel() {
    if (threadIdx.x < AA) g_count[threadIdx.x] = 0;
}

// ---------------- kernel 1: argmax + gather + copy + bucket ----------------
__global__ __launch_bounds__(256) void prep_kernel(const float* __restrict__ x,
                                                   const int* __restrict__ act,
                                                   float* __restrict__ out) {
    int warp = (blockIdx.x * blockDim.x + threadIdx.x) >> 5;
    int lane = threadIdx.x & 31;
    if (warp >= BB) return;
    const float* row = x + (size_t)warp * XX;
    float* orow = out + (size_t)warp * XX;

    float bestv = -3.402823466e38f;
    int besti = 0;
    for (int i = lane; i < XX; i += 32) {
        float v = row[i];
        orow[i] = v;                       // fused copy x -> out
        if (v > bestv) { bestv = v; besti = i; }
    }
    // warp argmax, first-occurrence tie-break (matches jnp.argmax)
    #pragma unroll
    for (int off = 16; off; off >>= 1) {
        float ov = __shfl_xor_sync(0xffffffffu, bestv, off);
        int   oi = __shfl_xor_sync(0xffffffffu, besti, off);
        if (ov > bestv || (ov == bestv && oi < besti)) { bestv = ov; besti = oi; }
    }
    int ptr = besti;   // identical in all lanes after butterfly

    if (lane < 6) {
        int t;
        switch (lane) {
            case 0: t = 0;        break;
            case 1: t = ptr;      break;   // unclamped, as in source
            case 2: t = ptr - GS; break;
            case 3: t = ptr + GS; break;
            case 4: t = ptr - 1;  break;
            default: t = ptr + 1; break;
        }
        if (lane >= 2) t = min(max(t, 1), XX - 1);
        g_idx[warp * 6 + lane] = t;
        g_att[warp * 6 + lane] = row[t];
    }
    if (lane == 0) {
        int a = act[warp];
        int slot = atomicAdd(&g_count[a], 1);
        g_perm[a * BB + slot] = warp;
    }
}

// ---------------- kernel 2: bucketed MLP (tf32 MMA) + scatter ----------------
// smem layout (floats):
//   sAtt  [128*8]       4096 B
//   sH1   [128*108]    55296 B   (h1, later reused for h3)
//   sW    [128*132]    67584 B   (W2 chunk / W3 chunk, alternating)
//   sH2   [128*132]    67584 B   (relu'd h2 chunk, tf32)
//   sPred [128*6]       3072 B
//   sRIdx [128 ints]     512 B
#define SMEM_FLOATS (128*8 + 128*STRH1 + 128*STRW + 128*STRH2 + 128*6 + 128)
#define SMEM_BYTES  (SMEM_FLOATS * 4)

__global__ __launch_bounds__(256, 1) void mlp_kernel(
    const float* __restrict__ xg,
    const float* __restrict__ W1g, const float* __restrict__ b1g,
    const float* __restrict__ W2g, const float* __restrict__ b2g,
    const float* __restrict__ W3g, const float* __restrict__ b3g,
    const float* __restrict__ W4g, const float* __restrict__ b4g,
    float* __restrict__ out)
{
    extern __shared__ float sm[];
    float* sAtt  = sm;
    float* sH1   = sAtt + 128 * 8;
    float* sW    = sH1 + 128 * STRH1;
    float* sH2   = sW + 128 * STRW;
    float* sPred = sH2 + 128 * STRH2;
    int*   sRIdx = (int*)(sPred + 128 * 6);

    const int a    = blockIdx.x / TILES;
    const int tile = blockIdx.x % TILES;
    const int base = tile * MT;
    const int cnt  = g_count[a];
    if (base >= cnt) return;
    const int mrows = min(MT, cnt - base);

    const int tid  = threadIdx.x;
    const int lane = tid & 31;
    const int w    = tid >> 5;
    const int g    = lane >> 2;
    const int tig  = lane & 3;
    const int mr   = w * 16;

    if (tid < MT) sRIdx[tid] = (tid < mrows) ? g_perm[a * BB + base + tid] : 0;
    __syncthreads();

    for (int i = tid; i < MT * 8; i += 256) {
        int r = i >> 3, k = i & 7;
        sAtt[i] = (k < 6 && r < mrows) ? g_att[sRIdx[r] * 6 + k] : 0.f;
    }
    __syncthreads();

    // ---- L1: scalar fp32 [128,6]@[6,100] -> sH1 (tf32-rounded), pad cols 100..103 = 0
    {
        const float* W1a = W1g + a * 600;
        const float* b1a = b1g + a * 100;
        for (int o = tid; o < MT * 104; o += 256) {
            int r = o / 104, u = o - r * 104;
            float v = 0.f;
            if (u < 100) {
                float acc = b1a[u];
                #pragma unroll
                for (int k = 0; k < 6; k++) acc += sAtt[r * 8 + k] * W1a[k * 100 + u];
                v = fmaxf(acc, 0.f);
            }
            sH1[r * STRH1 + u] = __uint_as_float(tf32r(v));
        }
    }

    // persistent h3 accumulators: warp rows [mr, mr+16), 13 n8 tiles (N padded 100->104)
    float c3[13][4];
    #pragma unroll
    for (int nt = 0; nt < 13; nt++)
        #pragma unroll
        for (int e = 0; e < 4; e++) c3[nt][e] = 0.f;

    const float* W2a = W2g + a * 40000;
    const float* W3a = W3g + a * 40000;
    const float* b2a = b2g + a * 400;

    // ---- fused L2/L3 over 4 chunks of 128 h2-columns (400 padded to 512)
    for (int c = 0; c < 4; c++) {
        __syncthreads();  // sH1 stores (iter 0) / previous L3 reads of sW & sH2 complete
        // load W2 chunk [k<104][j'<128] into sW
        for (int e = tid; e < 104 * 128; e += 256) {
            int k = e >> 7, j2 = e & 127;
            int j = c * 128 + j2;
            float v = (k < 100 && j < 400) ? W2a[k * 400 + j] : 0.f;
            sW[k * STRW + j2] = __uint_as_float(tf32r(v));
        }
        __syncthreads();

        // L2 MMA: [16,104]@[104,128] per warp
        float c2[16][4];
        #pragma unroll
        for (int nt = 0; nt < 16; nt++)
            #pragma unroll
            for (int e = 0; e < 4; e++) c2[nt][e] = 0.f;

        for (int ks = 0; ks < 13; ks++) {
            int ka = ks * 8;
            unsigned a0 = __float_as_uint(sH1[(mr + g)     * STRH1 + ka + tig]);
            unsigned a1 = __float_as_uint(sH1[(mr + g + 8) * STRH1 + ka + tig]);
            unsigned a2 = __float_as_uint(sH1[(mr + g)     * STRH1 + ka + tig + 4]);
            unsigned a3 = __float_as_uint(sH1[(mr + g + 8) * STRH1 + ka + tig + 4]);
            #pragma unroll
            for (int nt = 0; nt < 16; nt++) {
                unsigned b0 = __float_as_uint(sW[(ka + tig)     * STRW + nt * 8 + g]);
                unsigned b1 = __float_as_uint(sW[(ka + tig + 4) * STRW + nt * 8 + g]);
                mma_tf32(c2[nt], a0, a1, a2, a3, b0, b1);
            }
        }

        // epilogue: h2 = tf32(relu(c2 + b2)) -> sH2 (own rows, no race with other warps' L2)
        #pragma unroll
        for (int nt = 0; nt < 16; nt++) {
            #pragma unroll
            for (int e = 0; e < 4; e++) {
                int rr  = mr + g + ((e >> 1) ? 8 : 0);
                int col = nt * 8 + 2 * tig + (e & 1);
                int j   = c * 128 + col;
                float v = c2[nt][e] + ((j < 400) ? b2a[j] : 0.f);
                v = fmaxf(v, 0.f);
                sH2[rr * STRH2 + col] = __uint_as_float(tf32r(v));
            }
        }
        __syncthreads();  // all L2 reads of sW + all sH2 stores done

        // load W3 chunk [j'<128][n<104] into sW
        for (int e = tid; e < 128 * 104; e += 256) {
            int j2 = e / 104, n = e - j2 * 104;
            int j = c * 128 + j2;
            float v = (j < 400 && n < 100) ? W3a[j * 100 + n] : 0.f;
            sW[j2 * STRW + n] = __uint_as_float(tf32r(v));
        }
        __syncthreads();

        // L3 MMA accumulate: [16,128]@[128,104] per warp
        for (int ks = 0; ks < 16; ks++) {
            int ka = ks * 8;
            unsigned a0 = __float_as_uint(sH2[(mr + g)     * STRH2 + ka + tig]);
            unsigned a1 = __float_as_uint(sH2[(mr + g + 8) * STRH2 + ka + tig]);
            unsigned a2 = __float_as_uint(sH2[(mr + g)     * STRH2 + ka + tig + 4]);
            unsigned a3 = __float_as_uint(sH2[(mr + g + 8) * STRH2 + ka + tig + 4]);
            #pragma unroll
            for (int nt = 0; nt < 13; nt++) {
                unsigned b0 = __float_as_uint(sW[(ka + tig)     * STRW + nt * 8 + g]);
                unsigned b1 = __float_as_uint(sW[(ka + tig + 4) * STRW + nt * 8 + g]);
                mma_tf32(c3[nt], a0, a1, a2, a3, b0, b1);
            }
        }
    }
    __syncthreads();  // all reads of sH1 (L2) complete; safe to reuse as h3

    // ---- h3 = relu(c3 + b3) -> sH1 (fp32, scalar consumer)
    {
        const float* b3a = b3g + a * 100;
        #pragma unroll
        for (int nt = 0; nt < 13; nt++) {
            #pragma unroll
            for (int e = 0; e < 4; e++) {
                int rr = mr + g + ((e >> 1) ? 8 : 0);
                int n  = nt * 8 + 2 * tig + (e & 1);
                float v = c3[nt][e] + ((n < 100) ? b3a[n] : 0.f);
                sH1[rr * STRH1 + n] = fmaxf(v, 0.f);
            }
        }
    }
    __syncthreads();

    // ---- L4: scalar fp32 [128,100]@[100,6] -> sPred
    {
        const float* W4a = W4g + a * 600;
        const float* b4a = b4g + a * 6;
        for (int o = tid; o < MT * 6; o += 256) {
            int r = o / 6, j = o - r * 6;
            float acc = b4a[j];
            #pragma unroll 4
            for (int u = 0; u < 100; u++) acc += sH1[r * STRH1 + u] * W4a[u * 6 + j];
            sPred[o] = acc;
        }
    }
    __syncthreads();

    // ---- scatter: out[t] = x[t] + pred[j], last j wins on duplicate targets
    if (tid < mrows) {
        int row = sRIdx[tid];
        int   t[6];
        float p[6];
        #pragma unroll
        for (int j = 0; j < 6; j++) {
            t[j] = g_idx[row * 6 + j];
            p[j] = sPred[tid * 6 + j];
        }
        #pragma unroll
        for (int j = 0; j < 6; j++) {
            bool win = true;
            #pragma unroll
            for (int j2 = j + 1; j2 < 6; j2++)
                if (t[j2] == t[j]) win = false;
            if (win) out[(size_t)row * XX + t[j]] = xg[(size_t)row * XX + t[j]] + p[j];
        }
    }
}

// ---------------- launch ----------------
extern "C" void kernel_launch(void* const* d_in, const int* in_sizes, int n_in,
                              void* d_out, int out_size) {
    const float* x  = (const float*)d_in[0];
    const float* W1 = (const float*)d_in[1];
    const float* b1 = (const float*)d_in[2];
    const float* W2 = (const float*)d_in[3];
    const float* b2 = (const float*)d_in[4];
    const float* W3 = (const float*)d_in[5];
    const float* b3 = (const float*)d_in[6];
    const float* W4 = (const float*)d_in[7];
    const float* b4 = (const float*)d_in[8];
    const int*  act = (const int*)d_in[9];
    float* out = (float*)d_out;

    cudaFuncSetAttribute(mlp_kernel, cudaFuncAttributeMaxDynamicSharedMemorySize, SMEM_BYTES);

    zero_counts_kernel<<<1, 32>>>();
    prep_kernel<<<BB / 8, 256>>>(x, act, out);
    mlp_kernel<<<AA * TILES, 256, SMEM_BYTES>>>(x, W1, b1, W2, b2, W3, b3, W4, b4, out);
}

// round 6
// speedup vs baseline: 2.2277x; 2.2277x over previous
#include <cuda_runtime.h>
#include <cuda_fp16.h>
#include <cstdint>

#define BB 65536
#define XX 362
#define AA 3
#define GS 19

#define MT 256            // rows per MLP tile
#define TILES (BB / MT)   // 256
#define THREADS 512

#define STRH1 120         // fp16 stride for h1/h3 tile
#define STRW2 120         // W2 chunk [128 n][112 k]
#define STRW3 136         // W3 chunk [112 n][128 k]
#define STRH2 136         // h2 chunk [256 r][128 k]

// ---------------- device scratch ----------------
__device__ int   g_count[AA];
__device__ int   g_perm[AA * BB];
__device__ float g_att[BB * 6];
__device__ int   g_idx[BB * 6];

// ---------------- helpers ----------------
__device__ __forceinline__ void ldsm4(unsigned& r0, unsigned& r1, unsigned& r2, unsigned& r3,
                                      const __half* p) {
    unsigned addr = (unsigned)__cvta_generic_to_shared(p);
    asm volatile("ldmatrix.sync.aligned.m8n8.x4.shared.b16 {%0,%1,%2,%3}, [%4];"
                 : "=r"(r0), "=r"(r1), "=r"(r2), "=r"(r3) : "r"(addr));
}

__device__ __forceinline__ void mma16(float c[4], unsigned a0, unsigned a1, unsigned a2, unsigned a3,
                                      unsigned b0, unsigned b1) {
    asm volatile(
        "mma.sync.aligned.m16n8k16.row.col.f32.f16.f16.f32 "
        "{%0,%1,%2,%3}, {%4,%5,%6,%7}, {%8,%9}, {%0,%1,%2,%3};"
        : "+f"(c[0]), "+f"(c[1]), "+f"(c[2]), "+f"(c[3])
        : "r"(a0), "r"(a1), "r"(a2), "r"(a3), "r"(b0), "r"(b1));
}

// ---------------- kernel 0: reset counters ----------------
__global__ void zero_counts_kernel() {
    if (threadIdx.x < AA) g_count[threadIdx.x] = 0;
}

// ---------------- kernel 1: argmax + gather + copy + bucket (block-agg atomics) ----------------
__global__ __launch_bounds__(1024) void prep_kernel(const float* __restrict__ x,
                                                    const int* __restrict__ act,
                                                    float* __restrict__ out) {
    __shared__ int s_cnt[AA];
    __shared__ int s_base[AA];
    int tid  = threadIdx.x;
    int lane = tid & 31;
    int wib  = tid >> 5;                 // warp in block, 32 warps
    int row  = blockIdx.x * 32 + wib;    // one row per warp

    if (tid < AA) s_cnt[tid] = 0;
    __syncthreads();

    const float2* rp = (const float2*)(x + (size_t)row * XX);
    float2*       op = (float2*)(out + (size_t)row * XX);

    float bestv = -3.402823466e38f;
    int besti = 0;
    #pragma unroll 6
    for (int i = lane; i < XX / 2; i += 32) {   // 181 float2
        float2 v = rp[i];
        op[i] = v;                               // fused copy x -> out
        if (v.x > bestv) { bestv = v.x; besti = 2 * i; }
        if (v.y > bestv) { bestv = v.y; besti = 2 * i + 1; }
    }
    #pragma unroll
    for (int off = 16; off; off >>= 1) {
        float ov = __shfl_xor_sync(0xffffffffu, bestv, off);
        int   oi = __shfl_xor_sync(0xffffffffu, besti, off);
        if (ov > bestv || (ov == bestv && oi < besti)) { bestv = ov; besti = oi; }
    }
    int ptr = besti;

    if (lane < 6) {
        int t;
        switch (lane) {
            case 0: t = 0;        break;
            case 1: t = ptr;      break;   // unclamped, as in source
            case 2: t = ptr - GS; break;
            case 3: t = ptr + GS; break;
            case 4: t = ptr - 1;  break;
            default: t = ptr + 1; break;
        }
        if (lane >= 2) t = min(max(t, 1), XX - 1);
        g_idx[row * 6 + lane] = t;
        g_att[row * 6 + lane] = x[(size_t)row * XX + t];
    }

    int a = 0, slot = 0;
    if (lane == 0) {
        a = act[row];
        slot = atomicAdd(&s_cnt[a], 1);
    }
    __syncthreads();
    if (tid < AA) s_base[tid] = atomicAdd(&g_count[tid], s_cnt[tid]);
    __syncthreads();
    if (lane == 0) g_perm[a * BB + s_base[a] + slot] = row;
}

// ---------------- kernel 2: bucketed MLP (fp16 mma.sync + ldmatrix) ----------------
#define SMEM_BYTES (MT*8*4 + MT*STRH1*2 + 128*STRW3*2 + MT*STRH2*2 + MT*6*4 + MT*4)

__global__ __launch_bounds__(THREADS, 1) void mlp_kernel(
    const float* __restrict__ xg,
    const float* __restrict__ W1g, const float* __restrict__ b1g,
    const float* __restrict__ W2g, const float* __restrict__ b2g,
    const float* __restrict__ W3g, const float* __restrict__ b3g,
    const float* __restrict__ W4g, const float* __restrict__ b4g,
    float* __restrict__ out)
{
    extern __shared__ char smraw[];
    float*  sAtt  = (float*)smraw;                      // [256][8]
    __half* sH1   = (__half*)(sAtt + MT * 8);           // [256][STRH1]  h1, later h3
    __half* sW    = sH1 + MT * STRH1;                   // weight chunk (max 128*STRW3)
    __half* sH2   = sW + 128 * STRW3;                   // [256][STRH2]
    float*  sPred = (float*)(sH2 + MT * STRH2);         // [256][6]
    int*    sRIdx = (int*)(sPred + MT * 6);             // [256]

    const int a    = blockIdx.x / TILES;
    const int tile = blockIdx.x % TILES;
    const int base = tile * MT;
    const int cnt  = g_count[a];
    if (base >= cnt) return;
    const int mrows = min(MT, cnt - base);

    const int tid  = threadIdx.x;
    const int lane = tid & 31;
    const int w    = tid >> 5;
    const int g    = lane >> 2;
    const int tig  = lane & 3;
    const int mr   = w * 16;

    // per-lane ldmatrix source coords
    const int arow = (lane & 15);
    const int acol = (lane >> 4) << 3;
    const int brow = ((lane >> 4) << 3) + (lane & 7);
    const int bcol = lane & 8;

    if (tid < MT) sRIdx[tid] = (tid < mrows) ? g_perm[a * BB + base + tid] : 0;
    __syncthreads();

    for (int i = tid; i < MT * 8; i += THREADS) {
        int r = i >> 3, k = i & 7;
        sAtt[i] = (k < 6 && r < mrows) ? g_att[sRIdx[r] * 6 + k] : 0.f;
    }
    __syncthreads();

    // ---- L1: scalar fp32 -> fp16 h1, pad cols [100,112)
    {
        const float* W1a = W1g + a * 600;
        const float* b1a = b1g + a * 100;
        for (int o = tid; o < MT * 112; o += THREADS) {
            int r = o / 112, u = o - r * 112;
            float v = 0.f;
            if (u < 100) {
                float acc = b1a[u];
                #pragma unroll
                for (int k = 0; k < 6; k++) acc += sAtt[r * 8 + k] * W1a[k * 100 + u];
                v = fmaxf(acc, 0.f);
            }
            sH1[r * STRH1 + u] = __float2half(v);
        }
    }

    float c3[14][4];
    #pragma unroll
    for (int nt = 0; nt < 14; nt++)
        #pragma unroll
        for (int e = 0; e < 4; e++) c3[nt][e] = 0.f;

    const float* W2a = W2g + a * 40000;
    const float* W3a = W3g + a * 40000;
    const float* b2a = b2g + a * 400;

    for (int c = 0; c < 4; c++) {
        __syncthreads();
        // load W2 chunk as [n=j2<128][k<112] fp16 — GUARD j<400 (zero-pad cols 400..511)
        for (int e = tid; e < 112 * 128; e += THREADS) {
            int k = e >> 7, j2 = e & 127;
            int j = c * 128 + j2;
            float v = (k < 100 && j < 400) ? W2a[k * 400 + j] : 0.f;
            sW[j2 * STRW2 + k] = __float2half(v);
        }
        __syncthreads();

        // ---- L2 in two N-halves of 64 cols (register budget)
        #pragma unroll
        for (int nh = 0; nh < 2; nh++) {
            float c2[8][4];
            #pragma unroll
            for (int nt = 0; nt < 8; nt++)
                #pragma unroll
                for (int e = 0; e < 4; e++) c2[nt][e] = 0.f;

            #pragma unroll
            for (int ks = 0; ks < 7; ks++) {
                int ka = ks * 16;
                unsigned a0, a1, a2, a3;
                ldsm4(a0, a1, a2, a3, sH1 + (mr + arow) * STRH1 + ka + acol);
                #pragma unroll
                for (int nt2 = 0; nt2 < 4; nt2++) {
                    int nb = nh * 64 + nt2 * 16;
                    unsigned b0, b1, b2r, b3r;
                    ldsm4(b0, b1, b2r, b3r, sW + (nb + brow) * STRW2 + ka + bcol);
                    mma16(c2[nt2 * 2],     a0, a1, a2, a3, b0, b1);
                    mma16(c2[nt2 * 2 + 1], a0, a1, a2, a3, b2r, b3r);
                }
            }
            // epilogue -> sH2 (own rows only); GUARD j<400 for bias, zero pad cols
            #pragma unroll
            for (int nt = 0; nt < 8; nt++) {
                #pragma unroll
                for (int e = 0; e < 4; e++) {
                    int rr  = mr + g + ((e >> 1) ? 8 : 0);
                    int col = nh * 64 + nt * 8 + 2 * tig + (e & 1);
                    int j   = c * 128 + col;
                    float v = (j < 400) ? fmaxf(c2[nt][e] + b2a[j], 0.f) : 0.f;
                    sH2[rr * STRH2 + col] = __float2half(v);
                }
            }
        }
        __syncthreads();

        // load W3 chunk as [n<112][k<128] fp16 — GUARD j<400 (zero rows for pad cols)
        for (int e = tid; e < 112 * 128; e += THREADS) {
            int n = e % 112, k = e / 112;
            int j = c * 128 + k;
            float v = (j < 400 && n < 100) ? W3a[j * 100 + n] : 0.f;
            sW[n * STRW3 + k] = __float2half(v);
        }
        __syncthreads();

        // ---- L3 accumulate into c3
        #pragma unroll
        for (int ks = 0; ks < 8; ks++) {
            int ka = ks * 16;
            unsigned a0, a1, a2, a3;
            ldsm4(a0, a1, a2, a3, sH2 + (mr + arow) * STRH2 + ka + acol);
            #pragma unroll
            for (int ntp = 0; ntp < 7; ntp++) {
                int nb = ntp * 16;
                unsigned b0, b1, b2r, b3r;
                ldsm4(b0, b1, b2r, b3r, sW + (nb + brow) * STRW3 + ka + bcol);
                mma16(c3[ntp * 2],     a0, a1, a2, a3, b0, b1);
                mma16(c3[ntp * 2 + 1], a0, a1, a2, a3, b2r, b3r);
            }
        }
    }

    // ---- h3 = relu(c3 + b3) -> sH1 (fp16, own rows only)
    {
        const float* b3a = b3g + a * 100;
        #pragma unroll
        for (int nt = 0; nt < 13; nt++) {
            #pragma unroll
            for (int e = 0; e < 4; e++) {
                int rr = mr + g + ((e >> 1) ? 8 : 0);
                int n  = nt * 8 + 2 * tig + (e & 1);
                float v = c3[nt][e] + ((n < 100) ? b3a[n] : 0.f);
                sH1[rr * STRH1 + n] = __float2half(fmaxf(v, 0.f));
            }
        }
    }
    __syncthreads();

    // ---- L4: scalar fp32 [256,100]@[100,6] -> sPred
    {
        const float* W4a = W4g + a * 600;
        const float* b4a = b4g + a * 6;
        for (int o = tid; o < MT * 6; o += THREADS) {
            int r = o / 6, j = o - r * 6;
            float acc = b4a[j];
            #pragma unroll 4
            for (int u = 0; u < 100; u++)
                acc += __half2float(sH1[r * STRH1 + u]) * W4a[u * 6 + j];
            sPred[o] = acc;
        }
    }
    __syncthreads();

    // ---- scatter: out[t] = x[t] + pred[j], last j wins on duplicate targets
    if (tid < mrows) {
        int row = sRIdx[tid];
        int   t[6];
        float p[6];
        #pragma unroll
        for (int j = 0; j < 6; j++) {
            t[j] = g_idx[row * 6 + j];
            p[j] = sPred[tid * 6 + j];
        }
        #pragma unroll
        for (int j = 0; j < 6; j++) {
            bool win = true;
            #pragma unroll
            for (int j2 = j + 1; j2 < 6; j2++)
                if (t[j2] == t[j]) win = false;
            if (win) out[(size_t)row * XX + t[j]] = xg[(size_t)row * XX + t[j]] + p[j];
        }
    }
}

// ---------------- launch ----------------
extern "C" void kernel_launch(void* const* d_in, const int* in_sizes, int n_in,
                              void* d_out, int out_size) {
    const float* x  = (const float*)d_in[0];
    const float* W1 = (const float*)d_in[1];
    const float* b1 = (const float*)d_in[2];
    const float* W2 = (const float*)d_in[3];
    const float* b2 = (const float*)d_in[4];
    const float* W3 = (const float*)d_in[5];
    const float* b3 = (const float*)d_in[6];
    const float* W4 = (const float*)d_in[7];
    const float* b4 = (const float*)d_in[8];
    const int*  act = (const int*)d_in[9];
    float* out = (float*)d_out;

    cudaFuncSetAttribute(mlp_kernel, cudaFuncAttributeMaxDynamicSharedMemorySize, SMEM_BYTES);

    zero_counts_kernel<<<1, 32>>>();
    prep_kernel<<<BB / 32, 1024>>>(x, act, out);
    mlp_kernel<<<AA * TILES, THREADS, SMEM_BYTES>>>(x, W1, b1, W2, b2, W3, b3, W4, b4, out);
}

// round 7
// speedup vs baseline: 2.7859x; 1.2506x over previous
#include <cuda_runtime.h>
#include <cuda_fp16.h>
#include <cstdint>

#define BB 65536
#define XX 362
#define AA 3
#define GS 19

#define MT 256            // rows per MLP tile
#define TILES (BB / MT)   // 256
#define THREADS 512

#define STRH1 120         // fp16 stride for h1/h3 tile
#define STRW2 120         // W2 chunk [128 n][112 k]
#define STRW3 136         // W3 chunk [112 n][128 k]
#define STRH2 136         // h2 chunk [256 r][128 k]

// ---------------- device scratch ----------------
__device__ int    g_count[AA];
__device__ int    g_perm[AA * BB];
__device__ float  g_att[BB * 6];
__device__ int    g_idx[BB * 6];
// pre-converted fp16 weights, padded + transposed for direct cp.async
__device__ __half hW2c[AA * 512 * 112];   // [a][j(512)][k(112)]  = W2^T padded
__device__ __half hW3c[AA * 112 * 512];   // [a][n(112)][j(512)]  = W3^T padded

// ---------------- helpers ----------------
__device__ __forceinline__ void ldsm4(unsigned& r0, unsigned& r1, unsigned& r2, unsigned& r3,
                                      const __half* p) {
    unsigned addr = (unsigned)__cvta_generic_to_shared(p);
    asm volatile("ldmatrix.sync.aligned.m8n8.x4.shared.b16 {%0,%1,%2,%3}, [%4];"
                 : "=r"(r0), "=r"(r1), "=r"(r2), "=r"(r3) : "r"(addr));
}

__device__ __forceinline__ void mma16(float c[4], unsigned a0, unsigned a1, unsigned a2, unsigned a3,
                                      unsigned b0, unsigned b1) {
    asm volatile(
        "mma.sync.aligned.m16n8k16.row.col.f32.f16.f16.f32 "
        "{%0,%1,%2,%3}, {%4,%5,%6,%7}, {%8,%9}, {%0,%1,%2,%3};"
        : "+f"(c[0]), "+f"(c[1]), "+f"(c[2]), "+f"(c[3])
        : "r"(a0), "r"(a1), "r"(a2), "r"(a3), "r"(b0), "r"(b1));
}

__device__ __forceinline__ void cp16(__half* dst, const __half* src) {
    unsigned d = (unsigned)__cvta_generic_to_shared(dst);
    asm volatile("cp.async.cg.shared.global [%0], [%1], 16;" :: "r"(d), "l"(src));
}
#define CP_COMMIT() asm volatile("cp.async.commit_group;")
#define CP_WAIT1()  asm volatile("cp.async.wait_group 1;")
#define CP_WAIT0()  asm volatile("cp.async.wait_group 0;")

// ---------------- kernel 0: weight convert (+ counter reset) ----------------
// hW2c[a][j][k] = (j<400 && k<100) ? W2[a][k][j] : 0
// hW3c[a][n][j] = (n<100 && j<400) ? W3[a][j][n] : 0
#define NW2 (AA * 512 * 112)
#define NW3 (AA * 112 * 512)
__global__ __launch_bounds__(512) void convert_kernel(const float* __restrict__ W2g,
                                                      const float* __restrict__ W3g) {
    if (blockIdx.x == 0 && threadIdx.x < AA) g_count[threadIdx.x] = 0;
    int i = blockIdx.x * blockDim.x + threadIdx.x;
    if (i < NW2) {
        int a = i / (512 * 112), r = i % (512 * 112);
        int j = r / 112, k = r % 112;
        float v = (j < 400 && k < 100) ? W2g[a * 40000 + k * 400 + j] : 0.f;
        hW2c[i] = __float2half(v);
    } else if (i - NW2 < NW3) {
        int i2 = i - NW2;
        int a = i2 / (112 * 512), r = i2 % (112 * 512);
        int n = r / 512, j = r % 512;
        float v = (n < 100 && j < 400) ? W3g[a * 40000 + j * 100 + n] : 0.f;
        hW3c[i2] = __float2half(v);
    }
}

// ---------------- kernel 1: argmax + gather + copy + bucket (block-agg atomics) ----------------
__global__ __launch_bounds__(1024) void prep_kernel(const float* __restrict__ x,
                                                    const int* __restrict__ act,
                                                    float* __restrict__ out) {
    __shared__ int s_cnt[AA];
    __shared__ int s_base[AA];
    int tid  = threadIdx.x;
    int lane = tid & 31;
    int wib  = tid >> 5;
    int row  = blockIdx.x * 32 + wib;

    if (tid < AA) s_cnt[tid] = 0;
    __syncthreads();

    const float2* rp = (const float2*)(x + (size_t)row * XX);
    float2*       op = (float2*)(out + (size_t)row * XX);

    float bestv = -3.402823466e38f;
    int besti = 0;
    #pragma unroll 6
    for (int i = lane; i < XX / 2; i += 32) {
        float2 v = rp[i];
        op[i] = v;
        if (v.x > bestv) { bestv = v.x; besti = 2 * i; }
        if (v.y > bestv) { bestv = v.y; besti = 2 * i + 1; }
    }
    #pragma unroll
    for (int off = 16; off; off >>= 1) {
        float ov = __shfl_xor_sync(0xffffffffu, bestv, off);
        int   oi = __shfl_xor_sync(0xffffffffu, besti, off);
        if (ov > bestv || (ov == bestv && oi < besti)) { bestv = ov; besti = oi; }
    }
    int ptr = besti;

    if (lane < 6) {
        int t;
        switch (lane) {
            case 0: t = 0;        break;
            case 1: t = ptr;      break;   // unclamped, as in source
            case 2: t = ptr - GS; break;
            case 3: t = ptr + GS; break;
            case 4: t = ptr - 1;  break;
            default: t = ptr + 1; break;
        }
        if (lane >= 2) t = min(max(t, 1), XX - 1);
        g_idx[row * 6 + lane] = t;
        g_att[row * 6 + lane] = x[(size_t)row * XX + t];
    }

    int a = 0, slot = 0;
    if (lane == 0) {
        a = act[row];
        slot = atomicAdd(&s_cnt[a], 1);
    }
    __syncthreads();
    if (tid < AA) s_base[tid] = atomicAdd(&g_count[tid], s_cnt[tid]);
    __syncthreads();
    if (lane == 0) g_perm[a * BB + s_base[a] + slot] = row;
}

// ---------------- kernel 2: bucketed MLP (fp16 mma.sync + ldmatrix + cp.async pipeline) ----------------
#define SMEM_BYTES (MT*8*4 + MT*STRH1*2 + 128*STRW2*2 + 112*STRW3*2 + MT*STRH2*2 + MT*6*4 + MT*4)

__global__ __launch_bounds__(THREADS, 1) void mlp_kernel(
    const float* __restrict__ xg,
    const float* __restrict__ W1g, const float* __restrict__ b1g,
    const float* __restrict__ b2g, const float* __restrict__ b3g,
    const float* __restrict__ W4g, const float* __restrict__ b4g,
    float* __restrict__ out)
{
    extern __shared__ char smraw[];
    float*  sAtt  = (float*)smraw;                      // [256][8]
    __half* sH1   = (__half*)(sAtt + MT * 8);           // [256][STRH1]  h1, later h3
    __half* sW2   = sH1 + MT * STRH1;                   // [128][STRW2]
    __half* sW3   = sW2 + 128 * STRW2;                  // [112][STRW3]
    __half* sH2   = sW3 + 112 * STRW3;                  // [256][STRH2]
    float*  sPred = (float*)(sH2 + MT * STRH2);         // [256][6]
    int*    sRIdx = (int*)(sPred + MT * 6);             // [256]

    const int a    = blockIdx.x / TILES;
    const int tile = blockIdx.x % TILES;
    const int base = tile * MT;
    const int cnt  = g_count[a];
    if (base >= cnt) return;
    const int mrows = min(MT, cnt - base);

    const int tid  = threadIdx.x;
    const int lane = tid & 31;
    const int w    = tid >> 5;
    const int g    = lane >> 2;
    const int tig  = lane & 3;
    const int mr   = w * 16;

    const int arow = (lane & 15);
    const int acol = (lane >> 4) << 3;
    const int brow = ((lane >> 4) << 3) + (lane & 7);
    const int bcol = lane & 8;

    const __half* hw2 = hW2c + a * 512 * 112;
    const __half* hw3 = hW3c + a * 112 * 512;

    // ---- prefetch W2 chunk 0 (overlaps with sRIdx/sAtt/L1 below)
    {
        for (int e = tid; e < 1792; e += THREADS) {      // 128 rows x 14 x 16B
            int j2 = e / 14, s = e - j2 * 14;
            cp16(sW2 + j2 * STRW2 + s * 8, hw2 + j2 * 112 + s * 8);
        }
        CP_COMMIT();
    }

    if (tid < MT) sRIdx[tid] = (tid < mrows) ? g_perm[a * BB + base + tid] : 0;
    __syncthreads();

    for (int i = tid; i < MT * 8; i += THREADS) {
        int r = i >> 3, k = i & 7;
        sAtt[i] = (k < 6 && r < mrows) ? g_att[sRIdx[r] * 6 + k] : 0.f;
    }
    __syncthreads();

    // ---- L1: scalar fp32 -> fp16 h1, pad cols [100,112)
    {
        const float* W1a = W1g + a * 600;
        const float* b1a = b1g + a * 100;
        for (int o = tid; o < MT * 112; o += THREADS) {
            int r = o / 112, u = o - r * 112;
            float v = 0.f;
            if (u < 100) {
                float acc = b1a[u];
                #pragma unroll
                for (int k = 0; k < 6; k++) acc += sAtt[r * 8 + k] * W1a[k * 100 + u];
                v = fmaxf(acc, 0.f);
            }
            sH1[r * STRH1 + u] = __float2half(v);
        }
    }
    __syncthreads();   // sH1 ready

    float c3[14][4];
    #pragma unroll
    for (int nt = 0; nt < 14; nt++)
        #pragma unroll
        for (int e = 0; e < 4; e++) c3[nt][e] = 0.f;

    const float* b2a = b2g + a * 400;

    for (int c = 0; c < 4; c++) {
        // issue W3(c) load (overlaps with L2 MMA below)
        for (int e = tid; e < 1792; e += THREADS) {      // 112 rows x 16 x 16B
            int n = e >> 4, s = e & 15;
            cp16(sW3 + n * STRW3 + s * 8, hw3 + n * 512 + c * 128 + s * 8);
        }
        CP_COMMIT();

        CP_WAIT1();           // W2(c) arrived (W3(c) may be pending)
        __syncthreads();

        // ---- L2 in two N-halves of 64 cols (register budget)
        #pragma unroll
        for (int nh = 0; nh < 2; nh++) {
            float c2[8][4];
            #pragma unroll
            for (int nt = 0; nt < 8; nt++)
                #pragma unroll
                for (int e = 0; e < 4; e++) c2[nt][e] = 0.f;

            #pragma unroll
            for (int ks = 0; ks < 7; ks++) {
                int ka = ks * 16;
                unsigned a0, a1, a2, a3;
                ldsm4(a0, a1, a2, a3, sH1 + (mr + arow) * STRH1 + ka + acol);
                #pragma unroll
                for (int nt2 = 0; nt2 < 4; nt2++) {
                    int nb = nh * 64 + nt2 * 16;
                    unsigned b0, b1, b2r, b3r;
                    ldsm4(b0, b1, b2r, b3r, sW2 + (nb + brow) * STRW2 + ka + bcol);
                    mma16(c2[nt2 * 2],     a0, a1, a2, a3, b0, b1);
                    mma16(c2[nt2 * 2 + 1], a0, a1, a2, a3, b2r, b3r);
                }
            }
            // epilogue -> sH2 (own rows only); zero pad cols j>=400
            #pragma unroll
            for (int nt = 0; nt < 8; nt++) {
                #pragma unroll
                for (int e = 0; e < 4; e++) {
                    int rr  = mr + g + ((e >> 1) ? 8 : 0);
                    int col = nh * 64 + nt * 8 + 2 * tig + (e & 1);
                    int j   = c * 128 + col;
                    float v = (j < 400) ? fmaxf(c2[nt][e] + b2a[j], 0.f) : 0.f;
                    sH2[rr * STRH2 + col] = __float2half(v);
                }
            }
        }
        __syncthreads();      // sH2 ready; sW2 free

        // issue W2(c+1) load (overlaps with L3 MMA below)
        if (c < 3) {
            for (int e = tid; e < 1792; e += THREADS) {
                int j2 = e / 14, s = e - j2 * 14;
                cp16(sW2 + j2 * STRW2 + s * 8, hw2 + ((c + 1) * 128 + j2) * 112 + s * 8);
            }
            CP_COMMIT();
            CP_WAIT1();       // W3(c) arrived (W2(c+1) may be pending)
        } else {
            CP_WAIT0();       // last chunk: ensure W3(3) arrived
        }
        __syncthreads();

        // ---- L3 accumulate into c3
        #pragma unroll
        for (int ks = 0; ks < 8; ks++) {
            int ka = ks * 16;
            unsigned a0, a1, a2, a3;
            ldsm4(a0, a1, a2, a3, sH2 + (mr + arow) * STRH2 + ka + acol);
            #pragma unroll
            for (int ntp = 0; ntp < 7; ntp++) {
                int nb = ntp * 16;
                unsigned b0, b1, b2r, b3r;
                ldsm4(b0, b1, b2r, b3r, sW3 + (nb + brow) * STRW3 + ka + bcol);
                mma16(c3[ntp * 2],     a0, a1, a2, a3, b0, b1);
                mma16(c3[ntp * 2 + 1], a0, a1, a2, a3, b2r, b3r);
            }
        }
        __syncthreads();      // sW3 & sH2 free for next iteration
    }

    // ---- h3 = relu(c3 + b3) -> sH1 (fp16, own rows only)
    {
        const float* b3a = b3g + a * 100;
        #pragma unroll
        for (int nt = 0; nt < 13; nt++) {
            #pragma unroll
            for (int e = 0; e < 4; e++) {
                int rr = mr + g + ((e >> 1) ? 8 : 0);
                int n  = nt * 8 + 2 * tig + (e & 1);
                float v = c3[nt][e] + ((n < 100) ? b3a[n] : 0.f);
                sH1[rr * STRH1 + n] = __float2half(fmaxf(v, 0.f));
            }
        }
    }
    __syncthreads();

    // ---- L4: scalar fp32 [256,100]@[100,6] -> sPred
    {
        const float* W4a = W4g + a * 600;
        const float* b4a = b4g + a * 6;
        for (int o = tid; o < MT * 6; o += THREADS) {
            int r = o / 6, j = o - r * 6;
            float acc = b4a[j];
            #pragma unroll 4
            for (int u = 0; u < 100; u++)
                acc += __half2float(sH1[r * STRH1 + u]) * W4a[u * 6 + j];
            sPred[o] = acc;
        }
    }
    __syncthreads();

    // ---- scatter: out[t] = x[t] + pred[j], last j wins on duplicate targets
    if (tid < mrows) {
        int row = sRIdx[tid];
        int   t[6];
        float p[6];
        #pragma unroll
        for (int j = 0; j < 6; j++) {
            t[j] = g_idx[row * 6 + j];
            p[j] = sPred[tid * 6 + j];
        }
        #pragma unroll
        for (int j = 0; j < 6; j++) {
            bool win = true;
            #pragma unroll
            for (int j2 = j + 1; j2 < 6; j2++)
                if (t[j2] == t[j]) win = false;
            if (win) out[(size_t)row * XX + t[j]] = xg[(size_t)row * XX + t[j]] + p[j];
        }
    }
}

// ---------------- launch ----------------
extern "C" void kernel_launch(void* const* d_in, const int* in_sizes, int n_in,
                              void* d_out, int out_size) {
    const float* x  = (const float*)d_in[0];
    const float* W1 = (const float*)d_in[1];
    const float* b1 = (const float*)d_in[2];
    const float* W2 = (const float*)d_in[3];
    const float* b2 = (const float*)d_in[4];
    const float* W3 = (const float*)d_in[5];
    const float* b3 = (const float*)d_in[6];
    const float* W4 = (const float*)d_in[7];
    const float* b4 = (const float*)d_in[8];
    const int*  act = (const int*)d_in[9];
    float* out = (float*)d_out;

    cudaFuncSetAttribute(mlp_kernel, cudaFuncAttributeMaxDynamicSharedMemorySize, SMEM_BYTES);

    convert_kernel<<<(NW2 + NW3 + 511) / 512, 512>>>(W2, W3);
    prep_kernel<<<BB / 32, 1024>>>(x, act, out);
    mlp_kernel<<<AA * TILES, THREADS, SMEM_BYTES>>>(x, W1, b1, b2, b3, W4, b4, out);
}